// round 3
// baseline (speedup 1.0000x reference)
#include <cuda_runtime.h>
#include <cstdint>

#define BS 4
#define SQ 1024
#define CH 64
#define UN 32
#define TSPAN 72   // 8 query rows + 64 window

__device__ float g_q[BS * SQ * UN];
__device__ float g_k[BS * SQ * UN];

__device__ __forceinline__ float htanh(float x) {
    float y;
    asm("tanh.approx.f32 %0, %1;" : "=f"(y) : "f"(x));
    return y;
}

// ---------------------------------------------------------------------------
// Kernel 1: q[b,s,u] = sum_c x[b,c,s]*Wt[u,c];  k[b,s,u] = sum_c x*Wx + bh[u]
// block = 256 threads, handles (b, 32 consecutive s). grid = 4*32 = 128.
// 2x2 register tiling: 16x16 thread grid covers 32(u) x 32(s).
// ---------------------------------------------------------------------------
__global__ __launch_bounds__(256) void qk_kernel(const float* __restrict__ x,
                                                 const float* __restrict__ Wt,
                                                 const float* __restrict__ Wx,
                                                 const float* __restrict__ bh) {
    __shared__ __align__(16) float xs[CH * 36];   // [c][j]
    __shared__ __align__(16) float wts[CH * 36];  // [c][u]
    __shared__ __align__(16) float wxs[CH * 36];
    __shared__ float bhs[UN];

    int b = blockIdx.x >> 5;
    int s0 = (blockIdx.x & 31) << 5;
    int tid = threadIdx.x;

    for (int lin = tid; lin < CH * 32; lin += 256) {
        int c = lin >> 5, j = lin & 31;
        xs[c * 36 + j] = x[(size_t)b * CH * SQ + c * SQ + s0 + j];
    }
    for (int lin = tid; lin < UN * CH; lin += 256) {
        int u = lin >> 6, c = lin & 63;
        wts[c * 36 + u] = Wt[lin];
        wxs[c * 36 + u] = Wx[lin];
    }
    if (tid < UN) bhs[tid] = bh[tid];
    __syncthreads();

    int u0 = (tid & 15) * 2;
    int j0 = (tid >> 4) * 2;
    float qa[2][2] = {};
    float ka[2][2] = {};
#pragma unroll 8
    for (int c = 0; c < CH; c++) {
        float2 xv = *(const float2*)&xs[c * 36 + j0];
        float2 wt = *(const float2*)&wts[c * 36 + u0];
        float2 wx = *(const float2*)&wxs[c * 36 + u0];
        float xr[2] = {xv.x, xv.y};
        float wtr[2] = {wt.x, wt.y};
        float wxr[2] = {wx.x, wx.y};
#pragma unroll
        for (int r = 0; r < 2; r++) {
#pragma unroll
            for (int uu = 0; uu < 2; uu++) {
                qa[r][uu] = fmaf(xr[r], wtr[uu], qa[r][uu]);
                ka[r][uu] = fmaf(xr[r], wxr[uu], ka[r][uu]);
            }
        }
    }
#pragma unroll
    for (int r = 0; r < 2; r++) {
        size_t base = ((size_t)b * SQ + s0 + j0 + r) * UN + u0;
#pragma unroll
        for (int uu = 0; uu < 2; uu++) {
            g_q[base + uu] = qa[r][uu];
            g_k[base + uu] = ka[r][uu] + bhs[u0 + uu];  // fold bh into k
        }
    }
}

// ---------------------------------------------------------------------------
// Kernel 2: 512 threads = 16 warps = 8 query rows, TWO warps per row.
// Warp (r, h) owns window half h: lane ln handles j = h*32 + ln (one score).
// Cross-warp softmax via smem (max, sum). v partials via register shuffles.
// grid = 4 * 128 = 512 blocks.
// ---------------------------------------------------------------------------
__global__ __launch_bounds__(512) void attn_kernel(const float* __restrict__ x,
                                                   const float* __restrict__ wa,
                                                   float* __restrict__ vout,
                                                   float* __restrict__ aout) {
    __shared__ __align__(16) float ks[TSPAN * 36];   // [ti][u], pad 36
    __shared__ __align__(16) float xts[TSPAN * 66];  // [ti][c], pad 66
    __shared__ __align__(16) float qs[8 * 32];       // [r][u]
    __shared__ __align__(16) float a_s[8 * 64];      // [r][j]
    __shared__ __align__(16) float was[UN];
    __shared__ float maxbuf[8][2];
    __shared__ float sumbuf[8][2];
    __shared__ float vs[CH * 17];                    // [c][w2], pad 17

    int b = blockIdx.x >> 7;
    int s0 = (blockIdx.x & 127) << 3;
    int tid = threadIdx.x;
    int w2 = tid >> 5;          // 0..15
    int r = w2 >> 1;            // query row within block, 0..7
    int h = w2 & 1;             // window half
    int ln = tid & 31;
    int tlo = s0 - 32;

    if (tid < UN) was[tid] = wa[tid];
    if (tid < 8 * 32) qs[tid] = g_q[((size_t)b * SQ + s0 + (tid >> 5)) * UN + (tid & 31)];
    for (int lin = tid; lin < TSPAN * UN; lin += 512) {
        int ti = lin >> 5, u = lin & 31;
        int t = tlo + ti;
        ks[ti * 36 + u] = (t >= 0 && t < SQ) ? g_k[((size_t)b * SQ + t) * UN + u] : 0.f;
    }
    for (int lin = tid; lin < TSPAN * CH; lin += 512) {
        int c = lin / TSPAN, ti = lin - c * TSPAN;
        int t = tlo + ti;
        xts[ti * 66 + c] = (t >= 0 && t < SQ) ? x[(size_t)b * CH * SQ + c * SQ + t] : 0.f;
    }
    __syncthreads();

    int s = s0 + r;
    int j = h * 32 + ln;        // window offset of this lane
    int t = s - 32 + j;
    bool valid = (t >= 0) && (t < SQ);
    int ti = r + j;             // row in halo tile, <= 70

    // score for (s, t): sum_u wa[u]*tanh(q[u]+k[t][u])
    const float4* kp = (const float4*)&ks[ti * 36];
    const float4* qp = (const float4*)&qs[r * 32];
    const float4* wap = (const float4*)was;
    float acc = 0.f;
#pragma unroll
    for (int g = 0; g < 8; g++) {
        float4 q4 = qp[g];
        float4 w4 = wap[g];
        float4 k4 = kp[g];
        acc = fmaf(w4.x, htanh(q4.x + k4.x), acc);
        acc = fmaf(w4.y, htanh(q4.y + k4.y), acc);
        acc = fmaf(w4.z, htanh(q4.z + k4.z), acc);
        acc = fmaf(w4.w, htanh(q4.w + k4.w), acc);
    }
    float sc = valid ? acc : -1e30f;

    // warp-local max, then cross-warp (2 halves) via smem
    float m = sc;
#pragma unroll
    for (int o = 16; o > 0; o >>= 1) m = fmaxf(m, __shfl_xor_sync(0xffffffffu, m, o));
    if (ln == 0) maxbuf[r][h] = m;
    __syncthreads();
    m = fmaxf(maxbuf[r][0], maxbuf[r][1]);

    float e = valid ? __expf(sc - m) : 0.f;
    float sm = e;
#pragma unroll
    for (int o = 16; o > 0; o >>= 1) sm += __shfl_xor_sync(0xffffffffu, sm, o);
    if (ln == 0) sumbuf[r][h] = sm;
    __syncthreads();
    float inv = __fdividef(1.f, sumbuf[r][0] + sumbuf[r][1] + 1e-7f);
    float a = e * inv;
    a_s[(r << 6) + j] = a;

    // v partial over this warp's half-window, a values via shuffle
    // lane owns channels c = 2*ln, 2*ln+1
    float ax = 0.f, ay = 0.f;
#pragma unroll 8
    for (int jj = 0; jj < 32; jj++) {
        float av = __shfl_sync(0xffffffffu, a, jj);
        float2 xv = *(const float2*)&xts[(r + h * 32 + jj) * 66 + (ln << 1)];
        ax = fmaf(av, xv.x, ax);
        ay = fmaf(av, xv.y, ay);
    }
    vs[(ln * 2) * 17 + w2] = ax;
    vs[(ln * 2 + 1) * 17 + w2] = ay;
    __syncthreads();   // a_s complete + vs complete

    // full a row write: warp (r,h) writes cols [h*512, h*512+512)
    float4* arow = (float4*)(aout + (((size_t)b * SQ + s) << 10));
#pragma unroll
    for (int i = 0; i < 4; i++) {
        int col = (h << 9) + (i << 7) + (ln << 2);
        int jw = col - s + 32;
        float4 val;
        val.x = ((unsigned)(jw + 0) < 64u) ? a_s[(r << 6) + jw + 0] : 0.f;
        val.y = ((unsigned)(jw + 1) < 64u) ? a_s[(r << 6) + jw + 1] : 0.f;
        val.z = ((unsigned)(jw + 2) < 64u) ? a_s[(r << 6) + jw + 2] : 0.f;
        val.w = ((unsigned)(jw + 3) < 64u) ? a_s[(r << 6) + jw + 3] : 0.f;
        arow[col >> 2] = val;
    }

    // combine v halves + coalesced transposed write: v[b][c][s0..s0+8)
    {
        int c = tid >> 3, i = tid & 7;   // 512 threads cover 64*8
        float vsum = vs[c * 17 + i * 2] + vs[c * 17 + i * 2 + 1];
        vout[(size_t)b * CH * SQ + c * SQ + s0 + i] = vsum;
    }
}

extern "C" void kernel_launch(void* const* d_in, const int* in_sizes, int n_in,
                              void* d_out, int out_size) {
    (void)in_sizes; (void)n_in; (void)out_size;
    const float* x  = (const float*)d_in[0];
    const float* Wt = (const float*)d_in[1];
    const float* Wx = (const float*)d_in[2];
    const float* Wa = (const float*)d_in[3];
    // d_in[4] = Wa_b: cancels exactly in the softmax, unused
    const float* bh = (const float*)d_in[5];

    float* vout = (float*)d_out;                     // (B, C, S)
    float* aout = vout + (size_t)BS * CH * SQ;       // (B, S, S)

    qk_kernel<<<BS * 32, 256>>>(x, Wt, Wx, bh);
    attn_kernel<<<BS * 128, 512>>>(x, Wa, vout, aout);
}

// round 4
// speedup vs baseline: 1.1098x; 1.1098x over previous
#include <cuda_runtime.h>
#include <cstdint>

#define BS 4
#define SQ 1024
#define CH 64
#define UN 32
#define TSPAN 72   // 8 query rows + 64 window

__device__ float g_q[BS * SQ * UN];
__device__ float g_k[BS * SQ * UN];

__device__ __forceinline__ float htanh(float x) {
    float y;
    asm("tanh.approx.f32 %0, %1;" : "=f"(y) : "f"(x));
    return y;
}

// ---------------------------------------------------------------------------
// Kernel 1: q[b,s,u], k[b,s,u] (+bh). grid = 4*128 blocks, 256 threads,
// 8 s-rows per block, one (s,u) output pair per thread, float4 smem dots.
// ---------------------------------------------------------------------------
__global__ __launch_bounds__(256) void qk_kernel(const float* __restrict__ x,
                                                 const float* __restrict__ Wt,
                                                 const float* __restrict__ Wx,
                                                 const float* __restrict__ bh) {
    __shared__ __align__(16) float xs[8 * 68];    // [s][c]
    __shared__ __align__(16) float wts[UN * 68];  // [u][c]
    __shared__ __align__(16) float wxs[UN * 68];
    __shared__ float bhs[UN];

    int b = blockIdx.x >> 7;
    int s0 = (blockIdx.x & 127) << 3;
    int tid = threadIdx.x;

    for (int lin = tid; lin < 8 * CH; lin += 256) {
        int c = lin >> 3, s = lin & 7;
        xs[s * 68 + c] = x[(size_t)b * CH * SQ + c * SQ + s0 + s];
    }
    {
        const float4* wt4 = (const float4*)Wt;
        const float4* wx4 = (const float4*)Wx;
        for (int lin = tid; lin < UN * CH / 4; lin += 256) {
            int u = lin >> 4, g = lin & 15;
            *(float4*)&wts[u * 68 + g * 4] = wt4[lin];
            *(float4*)&wxs[u * 68 + g * 4] = wx4[lin];
        }
    }
    if (tid < UN) bhs[tid] = bh[tid];
    __syncthreads();

    int s = tid >> 5, u = tid & 31;
    float q0 = 0.f, q1 = 0.f, q2 = 0.f, q3 = 0.f;
    float k0 = 0.f, k1 = 0.f, k2 = 0.f, k3 = 0.f;
#pragma unroll
    for (int it = 0; it < 16; it++) {
        float4 x4 = *(const float4*)&xs[s * 68 + it * 4];
        float4 wt = *(const float4*)&wts[u * 68 + it * 4];
        float4 wx = *(const float4*)&wxs[u * 68 + it * 4];
        q0 = fmaf(x4.x, wt.x, q0); q1 = fmaf(x4.y, wt.y, q1);
        q2 = fmaf(x4.z, wt.z, q2); q3 = fmaf(x4.w, wt.w, q3);
        k0 = fmaf(x4.x, wx.x, k0); k1 = fmaf(x4.y, wx.y, k1);
        k2 = fmaf(x4.z, wx.z, k2); k3 = fmaf(x4.w, wx.w, k3);
    }
    size_t base = ((size_t)b * SQ + s0 + s) * UN + u;
    g_q[base] = (q0 + q1) + (q2 + q3);
    g_k[base] = (k0 + k1) + (k2 + k3) + bhs[u];  // fold bh into k
}

// ---------------------------------------------------------------------------
// Kernel 2: 512 threads = 16 warps = 8 query rows, 2 warps per row.
// Warp (r, h): lane ln owns score j = h*32 + ln. Clamped halo loads (masked
// scores / zero-weighted x rows keep results exact). Branch-light a-write.
// float4 v pass: per row 64 threads = 16 c-groups x 4 j-segments.
// ---------------------------------------------------------------------------
__global__ __launch_bounds__(512, 4) void attn_kernel(const float* __restrict__ x,
                                                      const float* __restrict__ wa,
                                                      float* __restrict__ vout,
                                                      float* __restrict__ aout) {
    __shared__ __align__(16) float ks[TSPAN * 36];   // [ti][u]
    __shared__ __align__(16) float xts[TSPAN * 68];  // [ti][c]
    __shared__ __align__(16) float qs[8 * 32];       // [r][u]
    __shared__ __align__(16) float a_s[8 * 64];      // [r][j]
    __shared__ __align__(16) float was[UN];
    __shared__ float maxbuf[8][2];
    __shared__ float sumbuf[8][2];
    __shared__ __align__(16) float vs[32 * 68];      // [(r*4+jseg)][c]

    int b = blockIdx.x >> 7;
    int s0 = (blockIdx.x & 127) << 3;
    int tid = threadIdx.x;
    int w2 = tid >> 5;          // 0..15
    int r = w2 >> 1;            // query row in block
    int h = w2 & 1;             // window half
    int ln = tid & 31;
    int tlo = s0 - 32;

    if (tid < UN) was[tid] = wa[tid];
    if (tid < 256) qs[tid] = g_q[((size_t)b * SQ + s0 + (tid >> 5)) * UN + (tid & 31)];
    {
        const float4* gk4 = (const float4*)g_k;
        for (int lin = tid; lin < TSPAN * UN / 4; lin += 512) {
            int ti = lin >> 3, g = lin & 7;
            int t = tlo + ti;
            int tc = min(max(t, 0), SQ - 1);
            *(float4*)&ks[ti * 36 + g * 4] = gk4[((size_t)b * SQ + tc) * 8 + g];
        }
    }
    for (int lin = tid; lin < TSPAN * CH; lin += 512) {
        int c = lin / TSPAN, ti = lin - c * TSPAN;
        int t = tlo + ti;
        int tc = min(max(t, 0), SQ - 1);
        xts[ti * 68 + c] = x[(size_t)b * CH * SQ + c * SQ + tc];
    }
    __syncthreads();

    int s = s0 + r;
    int j = h * 32 + ln;
    int t = s - 32 + j;
    bool valid = (t >= 0) && (t < SQ);
    int ti = r + j;             // <= 70

    const float4* kp = (const float4*)&ks[ti * 36];
    const float4* qp = (const float4*)&qs[r * 32];
    const float4* wap = (const float4*)was;
    float acc = 0.f;
#pragma unroll
    for (int g = 0; g < 8; g++) {
        float4 q4 = qp[g];
        float4 w4 = wap[g];
        float4 k4 = kp[g];
        acc = fmaf(w4.x, htanh(q4.x + k4.x), acc);
        acc = fmaf(w4.y, htanh(q4.y + k4.y), acc);
        acc = fmaf(w4.z, htanh(q4.z + k4.z), acc);
        acc = fmaf(w4.w, htanh(q4.w + k4.w), acc);
    }
    float sc = valid ? acc : -1e30f;

    float m = sc;
#pragma unroll
    for (int o = 16; o > 0; o >>= 1) m = fmaxf(m, __shfl_xor_sync(0xffffffffu, m, o));
    if (ln == 0) maxbuf[r][h] = m;
    __syncthreads();
    m = fmaxf(maxbuf[r][0], maxbuf[r][1]);

    float e = valid ? __expf(sc - m) : 0.f;
    float sm = e;
#pragma unroll
    for (int o = 16; o > 0; o >>= 1) sm += __shfl_xor_sync(0xffffffffu, sm, o);
    if (ln == 0) sumbuf[r][h] = sm;
    __syncthreads();
    float inv = __fdividef(1.f, sumbuf[r][0] + sumbuf[r][1] + 1e-7f);
    float a = e * inv;
    a_s[(r << 6) + j] = a;
    __syncthreads();   // a_s complete (read cross-warp below)

    // --- a row write: warp-uniform branch; window hits <=2 of 8 segments ---
    float4 z4 = make_float4(0.f, 0.f, 0.f, 0.f);
    float4* arow = (float4*)(aout + (((size_t)b * SQ + s) << 10));
#pragma unroll
    for (int i = 0; i < 4; i++) {
        int col0 = (h << 9) + (i << 7);   // warp-uniform segment start
        int col = col0 + (ln << 2);
        if (col0 > s + 31 || col0 + 127 < s - 32) {
            arow[col >> 2] = z4;
        } else {
            int jw = col - s + 32;
            float4 val;
            val.x = ((unsigned)(jw + 0) < 64u) ? a_s[(r << 6) + jw + 0] : 0.f;
            val.y = ((unsigned)(jw + 1) < 64u) ? a_s[(r << 6) + jw + 1] : 0.f;
            val.z = ((unsigned)(jw + 2) < 64u) ? a_s[(r << 6) + jw + 2] : 0.f;
            val.w = ((unsigned)(jw + 3) < 64u) ? a_s[(r << 6) + jw + 3] : 0.f;
            arow[col >> 2] = val;
        }
    }

    // --- v pass: per row, 64 threads = 16 channel-groups x 4 j-segments ---
    {
        int q64 = tid & 63;
        int cgrp = q64 & 15;      // 4 channels
        int jseg = q64 >> 4;      // 16 j each
        float4 vacc = z4;
#pragma unroll
        for (int it = 0; it < 16; it++) {
            int jj = jseg * 16 + it;
            float av = a_s[(r << 6) + jj];
            float4 x4 = *(const float4*)&xts[(r + jj) * 68 + (cgrp << 2)];
            vacc.x = fmaf(av, x4.x, vacc.x);
            vacc.y = fmaf(av, x4.y, vacc.y);
            vacc.z = fmaf(av, x4.z, vacc.z);
            vacc.w = fmaf(av, x4.w, vacc.w);
        }
        *(float4*)&vs[((r << 2) + jseg) * 68 + (cgrp << 2)] = vacc;
    }
    __syncthreads();

    // combine 4 j-segment partials + coalesced transposed v write
    {
        int c = tid >> 3, i = tid & 7;
        float vsum = (vs[(i * 4 + 0) * 68 + c] + vs[(i * 4 + 1) * 68 + c]) +
                     (vs[(i * 4 + 2) * 68 + c] + vs[(i * 4 + 3) * 68 + c]);
        vout[(size_t)b * CH * SQ + c * SQ + s0 + i] = vsum;
    }
}

extern "C" void kernel_launch(void* const* d_in, const int* in_sizes, int n_in,
                              void* d_out, int out_size) {
    (void)in_sizes; (void)n_in; (void)out_size;
    const float* x  = (const float*)d_in[0];
    const float* Wt = (const float*)d_in[1];
    const float* Wx = (const float*)d_in[2];
    const float* Wa = (const float*)d_in[3];
    // d_in[4] = Wa_b: cancels exactly in the softmax, unused
    const float* bh = (const float*)d_in[5];

    float* vout = (float*)d_out;                     // (B, C, S)
    float* aout = vout + (size_t)BS * CH * SQ;       // (B, S, S)

    qk_kernel<<<BS * 128, 256>>>(x, Wt, Wx, bh);
    attn_kernel<<<BS * 128, 512>>>(x, Wa, vout, aout);
}

// round 5
// speedup vs baseline: 1.1235x; 1.0123x over previous
#include <cuda_runtime.h>
#include <cstdint>

#define BS 4
#define SQ 1024
#define CH 64
#define UN 32
#define TSPAN 72   // 8 query rows + 64 window

__device__ float g_q[BS * SQ * UN];
__device__ float g_k[BS * SQ * UN];

__device__ __forceinline__ float htanh(float x) {
    float y;
    asm("tanh.approx.f32 %0, %1;" : "=f"(y) : "f"(x));
    return y;
}

// ---------------------------------------------------------------------------
// Kernel 1: q[b,s,u], k[b,s,u] (+bh). grid = 4*128 blocks, 256 threads,
// 8 s-rows per block, one (s,u) output pair per thread, float4 smem dots.
// ---------------------------------------------------------------------------
__global__ __launch_bounds__(256) void qk_kernel(const float* __restrict__ x,
                                                 const float* __restrict__ Wt,
                                                 const float* __restrict__ Wx,
                                                 const float* __restrict__ bh) {
    __shared__ __align__(16) float xs[8 * 68];    // [s][c]
    __shared__ __align__(16) float wts[UN * 68];  // [u][c]
    __shared__ __align__(16) float wxs[UN * 68];
    __shared__ float bhs[UN];

    int b = blockIdx.x >> 7;
    int s0 = (blockIdx.x & 127) << 3;
    int tid = threadIdx.x;

    for (int lin = tid; lin < 8 * CH; lin += 256) {
        int c = lin >> 3, s = lin & 7;
        xs[s * 68 + c] = x[(size_t)b * CH * SQ + c * SQ + s0 + s];
    }
    {
        const float4* wt4 = (const float4*)Wt;
        const float4* wx4 = (const float4*)Wx;
        for (int lin = tid; lin < UN * CH / 4; lin += 256) {
            int u = lin >> 4, g = lin & 15;
            *(float4*)&wts[u * 68 + g * 4] = wt4[lin];
            *(float4*)&wxs[u * 68 + g * 4] = wx4[lin];
        }
    }
    if (tid < UN) bhs[tid] = bh[tid];
    __syncthreads();

    int s = tid >> 5, u = tid & 31;
    float q0 = 0.f, q1 = 0.f, q2 = 0.f, q3 = 0.f;
    float k0 = 0.f, k1 = 0.f, k2 = 0.f, k3 = 0.f;
#pragma unroll
    for (int it = 0; it < 16; it++) {
        float4 x4 = *(const float4*)&xs[s * 68 + it * 4];
        float4 wt = *(const float4*)&wts[u * 68 + it * 4];
        float4 wx = *(const float4*)&wxs[u * 68 + it * 4];
        q0 = fmaf(x4.x, wt.x, q0); q1 = fmaf(x4.y, wt.y, q1);
        q2 = fmaf(x4.z, wt.z, q2); q3 = fmaf(x4.w, wt.w, q3);
        k0 = fmaf(x4.x, wx.x, k0); k1 = fmaf(x4.y, wx.y, k1);
        k2 = fmaf(x4.z, wx.z, k2); k3 = fmaf(x4.w, wx.w, k3);
    }
    size_t base = ((size_t)b * SQ + s0 + s) * UN + u;
    g_q[base] = (q0 + q1) + (q2 + q3);
    g_k[base] = (k0 + k1) + (k2 + k3) + bhs[u];  // fold bh into k
}

// ---------------------------------------------------------------------------
// Kernel 2: 512 threads = 16 warps = 8 query rows, 2 warps per row.
// k stored transposed in smem (pad 73: conflict-free both directions).
// No max-subtraction (scores bounded by sum|wa| ~ 4.5; shift cancels in
// softmax except through eps: rel err <= ~1.3e-5). Division-free loads.
// ---------------------------------------------------------------------------
__global__ __launch_bounds__(512, 4) void attn_kernel(const float* __restrict__ x,
                                                      const float* __restrict__ wa,
                                                      float* __restrict__ vout,
                                                      float* __restrict__ aout) {
    __shared__ float ks_t[UN * 73];                  // [u][ti], pad 73
    __shared__ __align__(16) float xts[TSPAN * 68];  // [ti][c], pad 68
    __shared__ __align__(16) float qs[8 * 32];       // [r][u]
    __shared__ __align__(16) float a_s[8 * 64];      // [r][j]
    __shared__ __align__(16) float was[UN];
    __shared__ float sumbuf[8][2];
    __shared__ __align__(16) float vs[32 * 68];      // [(r*4+jseg)][c]

    int b = blockIdx.x >> 7;
    int s0 = (blockIdx.x & 127) << 3;
    int tid = threadIdx.x;
    int w2 = tid >> 5;          // 0..15
    int r = w2 >> 1;            // query row in block
    int h = w2 & 1;             // window half
    int ln = tid & 31;
    int tlo = s0 - 32;

    if (tid < UN) was[tid] = wa[tid];
    if (tid < 256) qs[tid] = g_q[((size_t)b * SQ + s0 + (tid >> 5)) * UN + (tid & 31)];

    // k halo, transposed into smem (scatter conflict-free via pad 73)
    for (int lin = tid; lin < TSPAN * UN; lin += 512) {
        int u = lin & 31, ti = lin >> 5;
        int t = tlo + ti;
        int tc = min(max(t, 0), SQ - 1);
        ks_t[u * 73 + ti] = g_k[((size_t)b * SQ + tc) * UN + u];
    }

    // x halo: division-free, STS conflict-free, LDG sector-coalesced
    {
        int cc = tid >> 3;      // 0..63
        int t8 = tid & 7;
        const float* xb = x + (size_t)b * CH * SQ + cc * SQ;
#pragma unroll
        for (int p = 0; p < 9; p++) {
            int ti = p * 8 + t8;
            int t = tlo + ti;
            int tc = min(max(t, 0), SQ - 1);
            xts[ti * 68 + cc] = xb[tc];
        }
    }
    __syncthreads();

    int s = s0 + r;
    int j = h * 32 + ln;
    int t = s - 32 + j;
    bool valid = (t >= 0) && (t < SQ);
    int ti = r + j;             // <= 70

    const float4* qp = (const float4*)&qs[r * 32];
    const float4* wap = (const float4*)was;
    float acc = 0.f;
#pragma unroll
    for (int g = 0; g < 8; g++) {
        float4 q4 = qp[g];
        float4 w4 = wap[g];
        float k0 = ks_t[(g * 4 + 0) * 73 + ti];
        float k1 = ks_t[(g * 4 + 1) * 73 + ti];
        float k2 = ks_t[(g * 4 + 2) * 73 + ti];
        float k3 = ks_t[(g * 4 + 3) * 73 + ti];
        acc = fmaf(w4.x, htanh(q4.x + k0), acc);
        acc = fmaf(w4.y, htanh(q4.y + k1), acc);
        acc = fmaf(w4.z, htanh(q4.z + k2), acc);
        acc = fmaf(w4.w, htanh(q4.w + k3), acc);
    }

    // softmax without max-shift (scores bounded, shift cancels except eps)
    float e = valid ? __expf(acc) : 0.f;
    float sm = e;
#pragma unroll
    for (int o = 16; o > 0; o >>= 1) sm += __shfl_xor_sync(0xffffffffu, sm, o);
    if (ln == 0) sumbuf[r][h] = sm;
    __syncthreads();
    float inv = __fdividef(1.f, sumbuf[r][0] + sumbuf[r][1] + 1e-7f);
    float a = e * inv;
    a_s[(r << 6) + j] = a;
    __syncthreads();   // a_s complete (read cross-warp below)

    // --- a row write: warp-uniform branch; window hits <=2 of 8 segments ---
    float4 z4 = make_float4(0.f, 0.f, 0.f, 0.f);
    float4* arow = (float4*)(aout + (((size_t)b * SQ + s) << 10));
#pragma unroll
    for (int i = 0; i < 4; i++) {
        int col0 = (h << 9) + (i << 7);   // warp-uniform segment start
        int col = col0 + (ln << 2);
        if (col0 > s + 31 || col0 + 127 < s - 32) {
            arow[col >> 2] = z4;
        } else {
            int jw = col - s + 32;
            float4 val;
            val.x = ((unsigned)(jw + 0) < 64u) ? a_s[(r << 6) + jw + 0] : 0.f;
            val.y = ((unsigned)(jw + 1) < 64u) ? a_s[(r << 6) + jw + 1] : 0.f;
            val.z = ((unsigned)(jw + 2) < 64u) ? a_s[(r << 6) + jw + 2] : 0.f;
            val.w = ((unsigned)(jw + 3) < 64u) ? a_s[(r << 6) + jw + 3] : 0.f;
            arow[col >> 2] = val;
        }
    }

    // --- v pass: per row, 64 threads = 16 channel-groups x 4 j-segments ---
    {
        int q64 = tid & 63;
        int cgrp = q64 & 15;      // 4 channels
        int jseg = q64 >> 4;      // 16 j each
        float4 vacc = z4;
#pragma unroll
        for (int it = 0; it < 16; it++) {
            int jj = jseg * 16 + it;
            float av = a_s[(r << 6) + jj];
            float4 x4 = *(const float4*)&xts[(r + jj) * 68 + (cgrp << 2)];
            vacc.x = fmaf(av, x4.x, vacc.x);
            vacc.y = fmaf(av, x4.y, vacc.y);
            vacc.z = fmaf(av, x4.z, vacc.z);
            vacc.w = fmaf(av, x4.w, vacc.w);
        }
        *(float4*)&vs[((r << 2) + jseg) * 68 + (cgrp << 2)] = vacc;
    }
    __syncthreads();

    // combine 4 j-segment partials + coalesced transposed v write
    {
        int c = tid >> 3, i = tid & 7;
        float vsum = (vs[(i * 4 + 0) * 68 + c] + vs[(i * 4 + 1) * 68 + c]) +
                     (vs[(i * 4 + 2) * 68 + c] + vs[(i * 4 + 3) * 68 + c]);
        vout[(size_t)b * CH * SQ + c * SQ + s0 + i] = vsum;
    }
}

extern "C" void kernel_launch(void* const* d_in, const int* in_sizes, int n_in,
                              void* d_out, int out_size) {
    (void)in_sizes; (void)n_in; (void)out_size;
    const float* x  = (const float*)d_in[0];
    const float* Wt = (const float*)d_in[1];
    const float* Wx = (const float*)d_in[2];
    const float* Wa = (const float*)d_in[3];
    // d_in[4] = Wa_b: cancels exactly in the softmax, unused
    const float* bh = (const float*)d_in[5];

    float* vout = (float*)d_out;                     // (B, C, S)
    float* aout = vout + (size_t)BS * CH * SQ;       // (B, S, S)

    qk_kernel<<<BS * 128, 256>>>(x, Wt, Wx, bh);
    attn_kernel<<<BS * 128, 512>>>(x, Wa, vout, aout);
}